// round 13
// baseline (speedup 1.0000x reference)
#include <cuda_runtime.h>
#include <cuda_fp16.h>
#include <cstdint>
#include <cstddef>

// Problem shape (fixed by dataset)
#define NB   8192      // batch rows
#define DIM  4096      // in = out features
#define MAXN 0.99999f  // (1-EPS)/sqrt(C)

// ---------------- scratch (device globals; allocation-free) ----------------
__device__ __half g_xh[(size_t)NB * DIM];
__device__ __half g_wh[(size_t)DIM * DIM];
__device__ __half g_mx[(size_t)NB * DIM];   // raw GEMM result, fp16 staging
__device__ float g_xn[NB];     // raw row norms of x
__device__ float g_bm[DIM];    // expmap0(bias)
__device__ float g_y2s[1];     // ||bm||^2
__device__ float g_smm[NB];    // row sums of mx^2 (atomic)
__device__ float g_smb[NB];    // row sums of mx*bm (atomic)

// ---------------- PTX helpers (base sm_103 target ONLY: no tcgen05) --------
__device__ __forceinline__ uint32_t smem_u32(const void* p) {
    uint32_t a;
    asm("{ .reg .u64 t; cvta.to.shared.u64 t, %1; cvt.u32.u64 %0, t; }"
        : "=r"(a) : "l"(p));
    return a;
}

__device__ __forceinline__ void cp16(uint32_t dst, const void* src) {
    asm volatile("cp.async.cg.shared.global [%0], [%1], 16;" :: "r"(dst), "l"(src));
}

__device__ __forceinline__ void ldsm4(uint32_t* r, uint32_t addr) {
    asm volatile("ldmatrix.sync.aligned.m8n8.x4.shared.b16 {%0,%1,%2,%3}, [%4];"
                 : "=r"(r[0]), "=r"(r[1]), "=r"(r[2]), "=r"(r[3]) : "r"(addr));
}

__device__ __forceinline__ void mma_f16(float* c, const uint32_t* a,
                                        uint32_t b0, uint32_t b1) {
    asm volatile(
        "mma.sync.aligned.m16n8k16.row.col.f32.f16.f16.f32 "
        "{%0,%1,%2,%3}, {%4,%5,%6,%7}, {%8,%9}, {%0,%1,%2,%3};"
        : "+f"(c[0]), "+f"(c[1]), "+f"(c[2]), "+f"(c[3])
        : "r"(a[0]), "r"(a[1]), "r"(a[2]), "r"(a[3]), "r"(b0), "r"(b1));
}

#define SWZ(o) ((o) ^ (((o) >> 3) & 0x70))

// ---------------- prep: x->fp16(+norms,+zero sums), w->fp16, bias ----------
// blocks 0..NB-1: x rows; blocks NB..NB+4095: w chunks; block NB+4096: bias.
// Inputs are single-use: streaming loads (__ldcs) keep them out of L2 so the
// fp16 scratch (re-read by the GEMM) retains residency.
__global__ void k_prep(const float* __restrict__ x, const float* __restrict__ w,
                       const float* __restrict__ bias) {
    if (blockIdx.x < NB) {
        int r = blockIdx.x;
        const float4* row = (const float4*)(x + (size_t)r * DIM);
        __half2* orow = (__half2*)(g_xh + (size_t)r * DIM);
        float ss = 0.f;
        #pragma unroll
        for (int it = 0; it < 4; it++) {
            int c = it * 256 + threadIdx.x;
            float4 v = __ldcs(row + c);
            ss += v.x * v.x + v.y * v.y + v.z * v.z + v.w * v.w;
            orow[2 * c]     = __floats2half2_rn(v.x, v.y);
            orow[2 * c + 1] = __floats2half2_rn(v.z, v.w);
        }
        __shared__ float red[8];
        #pragma unroll
        for (int off = 16; off; off >>= 1) ss += __shfl_down_sync(0xffffffffu, ss, off);
        if ((threadIdx.x & 31) == 0) red[threadIdx.x >> 5] = ss;
        __syncthreads();
        if (threadIdx.x == 0) {
            float t = 0.f;
            #pragma unroll
            for (int i = 0; i < 8; i++) t += red[i];
            g_xn[r] = sqrtf(t);
            g_smm[r] = 0.f;              // zero the atomic accumulators (pre-GEMM)
            g_smb[r] = 0.f;
        }
    } else if (blockIdx.x < NB + 4096) {
        size_t blk = blockIdx.x - NB;                    // 0..4095
        const float4* w4 = (const float4*)w;
        __half2* o2 = (__half2*)g_wh;
        size_t b0 = blk * 1024;                          // 4096 blocks x 1024 float4
        #pragma unroll
        for (int it = 0; it < 4; it++) {
            size_t i = b0 + it * 256 + threadIdx.x;
            float4 v = __ldcs(w4 + i);
            o2[2 * i]     = __floats2half2_rn(v.x, v.y);
            o2[2 * i + 1] = __floats2half2_rn(v.z, v.w);
        }
    } else {
        // bias -> expmap0(bias) and ||bm||^2
        __shared__ float red[8];
        __shared__ float s_t;
        float ss = 0.f;
        for (int c = threadIdx.x; c < DIM; c += 256) { float v = bias[c]; ss += v * v; }
        #pragma unroll
        for (int off = 16; off; off >>= 1) ss += __shfl_down_sync(0xffffffffu, ss, off);
        if ((threadIdx.x & 31) == 0) red[threadIdx.x >> 5] = ss;
        __syncthreads();
        if (threadIdx.x == 0) {
            float t = 0.f;
            #pragma unroll
            for (int i = 0; i < 8; i++) t += red[i];
            float bn = fmaxf(sqrtf(t), 1e-15f);
            float th = tanhf(bn);
            s_t = th / bn;
            g_y2s[0] = th * th;
        }
        __syncthreads();
        float sc = s_t;
        for (int c = threadIdx.x; c < DIM; c += 256) g_bm[c] = sc * bias[c];
    }
}

// ---------------- GEMM (R7 core): mx = x @ W^T, fp16 out + atomic row sums --
// CTA tile 128(M) x 128(N) x 64(K), 8 warps (4x2, warp tile 32x64), 3-stage
// cp.async, 2 CTAs/SM, prefetch interleaved into ks loop. K=4096 -> 64 iters.
#define STAGES 3
#define NKIT   64
#define A_ST_BYTES 16384           // 128 rows x 128B
#define B_ST_BYTES 16384           // 128 rows x 128B
#define ST_BYTES   (A_ST_BYTES + B_ST_BYTES)   // 32 KB
#define SMEM_NEED  (STAGES * ST_BYTES + 1024)  // ~97 KB -> 2 CTAs/SM

__global__ void __launch_bounds__(256, 2)
k_gemm() {
    extern __shared__ char dsm[];
    uint32_t base = (smem_u32(dsm) + 1023u) & ~1023u;
    const int tid = threadIdx.x;
    const int wid = tid >> 5;
    const int lane = tid & 31;
    const int wm = wid >> 1;          // 0..3  (M direction, 32 rows each)
    const int wn = wid & 1;           // 0..1  (N direction, 64 cols each)

    // rasterize 64 x 32 tiles in 8x32 supertiles for L2 reuse
    int pid = blockIdx.x;
    int group = pid >> 8;             // / (8*32)
    int rem = pid & 255;
    int pm = group * 8 + (rem & 7);
    int pn = rem >> 3;
    const int m0 = pm * 128, n0 = pn * 128;

    // one A-chunk + one B-chunk of the stage, for pieces t = 0..3
    auto load_piece = [&](int s, int i, int t) {
        int koff = i * 64;                              // element offset in K
        size_t aBase = ((size_t)m0 * DIM + koff) * 2;
        size_t bBase = ((size_t)n0 * DIM + koff) * 2;
        uint32_t as = base + s * ST_BYTES;
        uint32_t bs = as + A_ST_BYTES;
        int chunk = t * 256 + tid;
        int row = chunk >> 3, c16 = chunk & 7;
        uint32_t so = SWZ(row * 128 + c16 * 16);
        size_t go = (size_t)row * (DIM * 2) + c16 * 16;
        cp16(as + so, (const char*)g_xh + aBase + go);
        cp16(bs + so, (const char*)g_wh + bBase + go);
    };

    auto load_stage = [&](int s, int i) {
        #pragma unroll
        for (int t = 0; t < 4; t++) load_piece(s, i, t);
    };

    // per-lane ldmatrix address components (within a stage)
    uint32_t arow[2], amask[2];
    #pragma unroll
    for (int mt = 0; mt < 2; mt++) {
        int row = wm * 32 + mt * 16 + (lane & 15);
        arow[mt] = row * 128;
        amask[mt] = (row & 7) << 4;
    }
    uint32_t akb = (lane >> 4) << 4;
    uint32_t brow[4], bmask[4];
    #pragma unroll
    for (int pr = 0; pr < 4; pr++) {
        int nrow = wn * 64 + pr * 16 + (lane & 7) + ((lane >> 4) << 3);
        brow[pr] = nrow * 128;
        bmask[pr] = (nrow & 7) << 4;
    }
    uint32_t bkb = ((lane >> 3) & 1) << 4;

    float acc[2][8][4];
    #pragma unroll
    for (int mt = 0; mt < 2; mt++)
        #pragma unroll
        for (int nt = 0; nt < 8; nt++)
            #pragma unroll
            for (int q = 0; q < 4; q++) acc[mt][nt][q] = 0.f;

    // prologue: load stages 0,1
    load_stage(0, 0);
    asm volatile("cp.async.commit_group;");
    load_stage(1, 1);
    asm volatile("cp.async.commit_group;");

    int s_cons = 0, s_load = 2;
    #pragma unroll 1
    for (int i = 0; i < NKIT; i++) {
        asm volatile("cp.async.wait_group 1;");
        __syncthreads();

        uint32_t aB = base + s_cons * ST_BYTES;
        uint32_t bB = aB + A_ST_BYTES;
        s_cons = (s_cons == 2) ? 0 : s_cons + 1;
        const bool pref = (i + 2 < NKIT);

        #pragma unroll
        for (int ks = 0; ks < 4; ks++) {
            uint32_t a[2][4], b[4][4];
            uint32_t ka = ks * 32 + akb;
            uint32_t kb = ks * 32 + bkb;
            #pragma unroll
            for (int mt = 0; mt < 2; mt++)
                ldsm4(a[mt], aB + arow[mt] + (ka ^ amask[mt]));
            #pragma unroll
            for (int pr = 0; pr < 4; pr++)
                ldsm4(b[pr], bB + brow[pr] + (kb ^ bmask[pr]));
            // interleaved prefetch: fills the ldsm->mma dependency shadow
            if (pref) load_piece(s_load, i + 2, ks);
            #pragma unroll
            for (int mt = 0; mt < 2; mt++)
                #pragma unroll
                for (int nt = 0; nt < 8; nt++)
                    mma_f16(acc[mt][nt], a[mt], b[nt >> 1][(nt & 1) * 2],
                            b[nt >> 1][(nt & 1) * 2 + 1]);
        }
        asm volatile("cp.async.commit_group;");        // uniform group accounting
        s_load = (s_load == 2) ? 0 : s_load + 1;
    }

    // ---- store raw mx tile as fp16 ----
    __half* hbase = g_mx + (size_t)(m0 + wm * 32) * DIM + n0 + wn * 64;
    int crow = lane >> 2;
    int ccol = (lane & 3) * 2;
    #pragma unroll
    for (int mt = 0; mt < 2; mt++)
        #pragma unroll
        for (int nt = 0; nt < 8; nt++)
            #pragma unroll
            for (int h = 0; h < 2; h++) {
                __half2 hv = __floats2half2_rn(acc[mt][nt][h * 2], acc[mt][nt][h * 2 + 1]);
                *(__half2*)(hbase + (size_t)(mt * 16 + crow + h * 8) * DIM + nt * 8 + ccol) = hv;
            }

    // ---- per-row partial sums (Smm, Smb) from fp32 accumulators ----
    {
        const float* bmp = g_bm + n0 + wn * 64;
        float bv[8][2];
        #pragma unroll
        for (int nt = 0; nt < 8; nt++) {
            bv[nt][0] = bmp[nt * 8 + ccol];
            bv[nt][1] = bmp[nt * 8 + ccol + 1];
        }
        #pragma unroll
        for (int mt = 0; mt < 2; mt++)
            #pragma unroll
            for (int h = 0; h < 2; h++) {
                float pmm = 0.f, pmb = 0.f;
                #pragma unroll
                for (int nt = 0; nt < 8; nt++) {
                    float v0 = acc[mt][nt][h * 2], v1 = acc[mt][nt][h * 2 + 1];
                    pmm += v0 * v0 + v1 * v1;
                    pmb += v0 * bv[nt][0] + v1 * bv[nt][1];
                }
                pmm += __shfl_xor_sync(0xffffffffu, pmm, 1);
                pmm += __shfl_xor_sync(0xffffffffu, pmm, 2);
                pmb += __shfl_xor_sync(0xffffffffu, pmb, 1);
                pmb += __shfl_xor_sync(0xffffffffu, pmb, 2);
                if ((lane & 3) == 0) {
                    int rg = m0 + wm * 32 + mt * 16 + h * 8 + crow;
                    atomicAdd(&g_smm[rg], pmm);
                    atomicAdd(&g_smb[rg], pmb);
                }
            }
    }
}

// ---------------- finisher: per-row coef (thread 0) + streaming rescale ----
__global__ void k_fin(float* __restrict__ out) {
    __shared__ float sk1, sk2;
    int r = blockIdx.x;
    if (threadIdx.x == 0) {
        float Smm = g_smm[r], Smb = g_smb[r];
        float xnraw = fmaxf(g_xn[r], 1e-15f);
        float s = (xnraw > MAXN) ? (MAXN / xnraw) : 1.f;
        float xn = fmaxf(fminf(xnraw, MAXN), 1e-15f);
        float mxn = fmaxf(s * sqrtf(Smm), 1e-15f);
        float at = atanhf(fminf(xn, 1.f - 1e-7f));
        float r_ = tanhf((mxn / xn) * at);
        float cres = r_ * s / mxn;            // res_i = cres * mx_raw_i
        float x2 = cres * cres * Smm;
        float xy = cres * Smb;
        float y2 = g_y2s[0];
        float A = 1.f + 2.f * xy + y2;
        float Bc = 1.f - x2;
        float den = fmaxf(1.f + 2.f * xy + x2 * y2, 1e-15f);
        float n2 = (A * A * x2 + 2.f * A * Bc * xy + Bc * Bc * y2) / (den * den);
        float on = fmaxf(sqrtf(fmaxf(n2, 0.f)), 1e-15f);
        float f = (on > MAXN) ? (MAXN / on) : 1.f;
        sk1 = f * A * cres / den;
        sk2 = f * Bc / den;
    }
    __syncthreads();
    float k1 = sk1, k2 = sk2;
    const uint2* mx = (const uint2*)(g_mx + (size_t)r * DIM);   // 4 halves / 8B
    const float4* bm4 = (const float4*)g_bm;
    float4* o = (float4*)(out + (size_t)r * DIM);
    #pragma unroll
    for (int it = 0; it < 4; it++) {
        int c = it * 256 + threadIdx.x;   // 0..1023 float4 per row
        uint2 m = __ldcs(mx + c);         // single-use: stream past L2
        float2 f0 = __half22float2(*(__half2*)&m.x);
        float2 f1 = __half22float2(*(__half2*)&m.y);
        float4 b = bm4[c];
        float4 v;
        v.x = k1 * f0.x + k2 * b.x;
        v.y = k1 * f0.y + k2 * b.y;
        v.z = k1 * f1.x + k2 * b.z;
        v.w = k1 * f1.y + k2 * b.w;
        __stcs(o + c, v);                 // never re-read by us: evict-first
    }
}

// ---------------- launch ----------------
extern "C" void kernel_launch(void* const* d_in, const int* in_sizes, int n_in,
                              void* d_out, int out_size) {
    const float* x = nullptr;
    const float* w = nullptr;
    const float* b = nullptr;
    for (int i = 0; i < n_in; i++) {
        if (in_sizes[i] == NB * DIM) x = (const float*)d_in[i];
        else if (in_sizes[i] == DIM * DIM) w = (const float*)d_in[i];
        else if (in_sizes[i] == DIM) b = (const float*)d_in[i];
    }
    float* out = (float*)d_out;

    k_prep<<<NB + 4096 + 1, 256>>>(x, w, b);

    cudaFuncSetAttribute(k_gemm, cudaFuncAttributeMaxDynamicSharedMemorySize, SMEM_NEED);
    k_gemm<<<2048, 256, SMEM_NEED>>>();

    k_fin<<<NB, 256>>>(out);
}

// round 14
// speedup vs baseline: 1.5017x; 1.5017x over previous
#include <cuda_runtime.h>
#include <cuda_fp16.h>
#include <cstdint>
#include <cstddef>

// Problem shape (fixed by dataset)
#define NB   8192      // batch rows
#define DIM  4096      // in = out features
#define MAXN 0.99999f  // (1-EPS)/sqrt(C)

// ---------------- scratch (device globals; allocation-free) ----------------
__device__ __half g_xh[(size_t)NB * DIM];
__device__ __half g_wh[(size_t)DIM * DIM];
__device__ __half g_mx[(size_t)NB * DIM];   // raw GEMM result, fp16 staging
__device__ float g_xn[NB];     // raw row norms of x
__device__ float g_bm[DIM];    // expmap0(bias)
__device__ float g_y2s[1];     // ||bm||^2
__device__ float g_smm[NB];    // row sums of mx^2 (atomic)
__device__ float g_smb[NB];    // row sums of mx*bm (atomic)

// ---------------- PTX helpers (base sm_103 target ONLY: no tcgen05) --------
__device__ __forceinline__ uint32_t smem_u32(const void* p) {
    uint32_t a;
    asm("{ .reg .u64 t; cvta.to.shared.u64 t, %1; cvt.u32.u64 %0, t; }"
        : "=r"(a) : "l"(p));
    return a;
}

__device__ __forceinline__ void cp16(uint32_t dst, const void* src) {
    asm volatile("cp.async.cg.shared.global [%0], [%1], 16;" :: "r"(dst), "l"(src));
}

__device__ __forceinline__ void ldsm4(uint32_t* r, uint32_t addr) {
    asm volatile("ldmatrix.sync.aligned.m8n8.x4.shared.b16 {%0,%1,%2,%3}, [%4];"
                 : "=r"(r[0]), "=r"(r[1]), "=r"(r[2]), "=r"(r[3]) : "r"(addr));
}

__device__ __forceinline__ void mma_f16(float* c, const uint32_t* a,
                                        uint32_t b0, uint32_t b1) {
    asm volatile(
        "mma.sync.aligned.m16n8k16.row.col.f32.f16.f16.f32 "
        "{%0,%1,%2,%3}, {%4,%5,%6,%7}, {%8,%9}, {%0,%1,%2,%3};"
        : "+f"(c[0]), "+f"(c[1]), "+f"(c[2]), "+f"(c[3])
        : "r"(a[0]), "r"(a[1]), "r"(a[2]), "r"(a[3]), "r"(b0), "r"(b1));
}

#define SWZ(o) ((o) ^ (((o) >> 3) & 0x70))

// ---------------- prep: x->fp16(+norms,+zero sums), w->fp16, bias ----------
// blocks 0..NB-1: x rows; blocks NB..NB+4095: w chunks; block NB+4096: bias.
__global__ void k_prep(const float* __restrict__ x, const float* __restrict__ w,
                       const float* __restrict__ bias) {
    if (blockIdx.x < NB) {
        int r = blockIdx.x;
        const float4* row = (const float4*)(x + (size_t)r * DIM);
        __half2* orow = (__half2*)(g_xh + (size_t)r * DIM);
        float ss = 0.f;
        #pragma unroll
        for (int it = 0; it < 4; it++) {
            int c = it * 256 + threadIdx.x;
            float4 v = row[c];
            ss += v.x * v.x + v.y * v.y + v.z * v.z + v.w * v.w;
            orow[2 * c]     = __floats2half2_rn(v.x, v.y);
            orow[2 * c + 1] = __floats2half2_rn(v.z, v.w);
        }
        __shared__ float red[8];
        #pragma unroll
        for (int off = 16; off; off >>= 1) ss += __shfl_down_sync(0xffffffffu, ss, off);
        if ((threadIdx.x & 31) == 0) red[threadIdx.x >> 5] = ss;
        __syncthreads();
        if (threadIdx.x == 0) {
            float t = 0.f;
            #pragma unroll
            for (int i = 0; i < 8; i++) t += red[i];
            g_xn[r] = sqrtf(t);
            g_smm[r] = 0.f;              // zero the atomic accumulators (pre-GEMM)
            g_smb[r] = 0.f;
        }
    } else if (blockIdx.x < NB + 4096) {
        size_t blk = blockIdx.x - NB;                    // 0..4095
        const float4* w4 = (const float4*)w;
        __half2* o2 = (__half2*)g_wh;
        size_t b0 = blk * 1024;                          // 4096 blocks x 1024 float4
        #pragma unroll
        for (int it = 0; it < 4; it++) {
            size_t i = b0 + it * 256 + threadIdx.x;
            float4 v = w4[i];
            o2[2 * i]     = __floats2half2_rn(v.x, v.y);
            o2[2 * i + 1] = __floats2half2_rn(v.z, v.w);
        }
    } else {
        // bias -> expmap0(bias) and ||bm||^2
        __shared__ float red[8];
        __shared__ float s_t;
        float ss = 0.f;
        for (int c = threadIdx.x; c < DIM; c += 256) { float v = bias[c]; ss += v * v; }
        #pragma unroll
        for (int off = 16; off; off >>= 1) ss += __shfl_down_sync(0xffffffffu, ss, off);
        if ((threadIdx.x & 31) == 0) red[threadIdx.x >> 5] = ss;
        __syncthreads();
        if (threadIdx.x == 0) {
            float t = 0.f;
            #pragma unroll
            for (int i = 0; i < 8; i++) t += red[i];
            float bn = fmaxf(sqrtf(t), 1e-15f);
            float th = tanhf(bn);
            s_t = th / bn;
            g_y2s[0] = th * th;
        }
        __syncthreads();
        float sc = s_t;
        for (int c = threadIdx.x; c < DIM; c += 256) g_bm[c] = sc * bias[c];
    }
}

// ---------------- GEMM (R7 core): mx = x @ W^T, fp16 out + atomic row sums --
// CTA tile 128(M) x 128(N) x 64(K), 8 warps (4x2, warp tile 32x64), 3-stage
// cp.async, 2 CTAs/SM, prefetch interleaved into ks loop. K=4096 -> 64 iters.
#define STAGES 3
#define NKIT   64
#define A_ST_BYTES 16384           // 128 rows x 128B
#define B_ST_BYTES 16384           // 128 rows x 128B
#define ST_BYTES   (A_ST_BYTES + B_ST_BYTES)   // 32 KB
#define SMEM_NEED  (STAGES * ST_BYTES + 1024)  // ~97 KB -> 2 CTAs/SM

__global__ void __launch_bounds__(256, 2)
k_gemm() {
    extern __shared__ char dsm[];
    uint32_t base = (smem_u32(dsm) + 1023u) & ~1023u;
    const int tid = threadIdx.x;
    const int wid = tid >> 5;
    const int lane = tid & 31;
    const int wm = wid >> 1;          // 0..3  (M direction, 32 rows each)
    const int wn = wid & 1;           // 0..1  (N direction, 64 cols each)

    // rasterize 64 x 32 tiles in 8x32 supertiles for L2 reuse
    int pid = blockIdx.x;
    int group = pid >> 8;             // / (8*32)
    int rem = pid & 255;
    int pm = group * 8 + (rem & 7);
    int pn = rem >> 3;
    const int m0 = pm * 128, n0 = pn * 128;

    // one A-chunk + one B-chunk of the stage, for pieces t = 0..3
    auto load_piece = [&](int s, int i, int t) {
        int koff = i * 64;                              // element offset in K
        size_t aBase = ((size_t)m0 * DIM + koff) * 2;
        size_t bBase = ((size_t)n0 * DIM + koff) * 2;
        uint32_t as = base + s * ST_BYTES;
        uint32_t bs = as + A_ST_BYTES;
        int chunk = t * 256 + tid;
        int row = chunk >> 3, c16 = chunk & 7;
        uint32_t so = SWZ(row * 128 + c16 * 16);
        size_t go = (size_t)row * (DIM * 2) + c16 * 16;
        cp16(as + so, (const char*)g_xh + aBase + go);
        cp16(bs + so, (const char*)g_wh + bBase + go);
    };

    auto load_stage = [&](int s, int i) {
        #pragma unroll
        for (int t = 0; t < 4; t++) load_piece(s, i, t);
    };

    // per-lane ldmatrix address components (within a stage)
    uint32_t arow[2], amask[2];
    #pragma unroll
    for (int mt = 0; mt < 2; mt++) {
        int row = wm * 32 + mt * 16 + (lane & 15);
        arow[mt] = row * 128;
        amask[mt] = (row & 7) << 4;
    }
    uint32_t akb = (lane >> 4) << 4;
    uint32_t brow[4], bmask[4];
    #pragma unroll
    for (int pr = 0; pr < 4; pr++) {
        int nrow = wn * 64 + pr * 16 + (lane & 7) + ((lane >> 4) << 3);
        brow[pr] = nrow * 128;
        bmask[pr] = (nrow & 7) << 4;
    }
    uint32_t bkb = ((lane >> 3) & 1) << 4;

    float acc[2][8][4];
    #pragma unroll
    for (int mt = 0; mt < 2; mt++)
        #pragma unroll
        for (int nt = 0; nt < 8; nt++)
            #pragma unroll
            for (int q = 0; q < 4; q++) acc[mt][nt][q] = 0.f;

    // prologue: load stages 0,1
    load_stage(0, 0);
    asm volatile("cp.async.commit_group;");
    load_stage(1, 1);
    asm volatile("cp.async.commit_group;");

    int s_cons = 0, s_load = 2;
    #pragma unroll 1
    for (int i = 0; i < NKIT; i++) {
        asm volatile("cp.async.wait_group 1;");
        __syncthreads();

        uint32_t aB = base + s_cons * ST_BYTES;
        uint32_t bB = aB + A_ST_BYTES;
        s_cons = (s_cons == 2) ? 0 : s_cons + 1;
        const bool pref = (i + 2 < NKIT);

        #pragma unroll
        for (int ks = 0; ks < 4; ks++) {
            uint32_t a[2][4], b[4][4];
            uint32_t ka = ks * 32 + akb;
            uint32_t kb = ks * 32 + bkb;
            #pragma unroll
            for (int mt = 0; mt < 2; mt++)
                ldsm4(a[mt], aB + arow[mt] + (ka ^ amask[mt]));
            #pragma unroll
            for (int pr = 0; pr < 4; pr++)
                ldsm4(b[pr], bB + brow[pr] + (kb ^ bmask[pr]));
            // interleaved prefetch: fills the ldsm->mma dependency shadow
            if (pref) load_piece(s_load, i + 2, ks);
            #pragma unroll
            for (int mt = 0; mt < 2; mt++)
                #pragma unroll
                for (int nt = 0; nt < 8; nt++)
                    mma_f16(acc[mt][nt], a[mt], b[nt >> 1][(nt & 1) * 2],
                            b[nt >> 1][(nt & 1) * 2 + 1]);
        }
        asm volatile("cp.async.commit_group;");        // uniform group accounting
        s_load = (s_load == 2) ? 0 : s_load + 1;
    }

    // ---- store raw mx tile as fp16 ----
    __half* hbase = g_mx + (size_t)(m0 + wm * 32) * DIM + n0 + wn * 64;
    int crow = lane >> 2;
    int ccol = (lane & 3) * 2;
    #pragma unroll
    for (int mt = 0; mt < 2; mt++)
        #pragma unroll
        for (int nt = 0; nt < 8; nt++)
            #pragma unroll
            for (int h = 0; h < 2; h++) {
                __half2 hv = __floats2half2_rn(acc[mt][nt][h * 2], acc[mt][nt][h * 2 + 1]);
                *(__half2*)(hbase + (size_t)(mt * 16 + crow + h * 8) * DIM + nt * 8 + ccol) = hv;
            }

    // ---- per-row partial sums (Smm, Smb) from fp32 accumulators ----
    {
        const float* bmp = g_bm + n0 + wn * 64;
        float bv[8][2];
        #pragma unroll
        for (int nt = 0; nt < 8; nt++) {
            bv[nt][0] = bmp[nt * 8 + ccol];
            bv[nt][1] = bmp[nt * 8 + ccol + 1];
        }
        #pragma unroll
        for (int mt = 0; mt < 2; mt++)
            #pragma unroll
            for (int h = 0; h < 2; h++) {
                float pmm = 0.f, pmb = 0.f;
                #pragma unroll
                for (int nt = 0; nt < 8; nt++) {
                    float v0 = acc[mt][nt][h * 2], v1 = acc[mt][nt][h * 2 + 1];
                    pmm += v0 * v0 + v1 * v1;
                    pmb += v0 * bv[nt][0] + v1 * bv[nt][1];
                }
                pmm += __shfl_xor_sync(0xffffffffu, pmm, 1);
                pmm += __shfl_xor_sync(0xffffffffu, pmm, 2);
                pmb += __shfl_xor_sync(0xffffffffu, pmb, 1);
                pmb += __shfl_xor_sync(0xffffffffu, pmb, 2);
                if ((lane & 3) == 0) {
                    int rg = m0 + wm * 32 + mt * 16 + h * 8 + crow;
                    atomicAdd(&g_smm[rg], pmm);
                    atomicAdd(&g_smb[rg], pmb);
                }
            }
    }
}

// ---------------- finisher: per-row coef (thread 0) + streaming rescale ----
__global__ void k_fin(float* __restrict__ out) {
    __shared__ float sk1, sk2;
    int r = blockIdx.x;
    if (threadIdx.x == 0) {
        float Smm = g_smm[r], Smb = g_smb[r];
        float xnraw = fmaxf(g_xn[r], 1e-15f);
        float s = (xnraw > MAXN) ? (MAXN / xnraw) : 1.f;
        float xn = fmaxf(fminf(xnraw, MAXN), 1e-15f);
        float mxn = fmaxf(s * sqrtf(Smm), 1e-15f);
        float at = atanhf(fminf(xn, 1.f - 1e-7f));
        float r_ = tanhf((mxn / xn) * at);
        float cres = r_ * s / mxn;            // res_i = cres * mx_raw_i
        float x2 = cres * cres * Smm;
        float xy = cres * Smb;
        float y2 = g_y2s[0];
        float A = 1.f + 2.f * xy + y2;
        float Bc = 1.f - x2;
        float den = fmaxf(1.f + 2.f * xy + x2 * y2, 1e-15f);
        float n2 = (A * A * x2 + 2.f * A * Bc * xy + Bc * Bc * y2) / (den * den);
        float on = fmaxf(sqrtf(fmaxf(n2, 0.f)), 1e-15f);
        float f = (on > MAXN) ? (MAXN / on) : 1.f;
        sk1 = f * A * cres / den;
        sk2 = f * Bc / den;
    }
    __syncthreads();
    float k1 = sk1, k2 = sk2;
    const uint2* mx = (const uint2*)(g_mx + (size_t)r * DIM);   // 4 halves / 8B
    const float4* bm4 = (const float4*)g_bm;
    float4* o = (float4*)(out + (size_t)r * DIM);
    #pragma unroll
    for (int it = 0; it < 4; it++) {
        int c = it * 256 + threadIdx.x;   // 0..1023 float4 per row
        uint2 m = mx[c];
        float2 f0 = __half22float2(*(__half2*)&m.x);
        float2 f1 = __half22float2(*(__half2*)&m.y);
        float4 b = bm4[c];
        float4 v;
        v.x = k1 * f0.x + k2 * b.x;
        v.y = k1 * f0.y + k2 * b.y;
        v.z = k1 * f1.x + k2 * b.z;
        v.w = k1 * f1.y + k2 * b.w;
        o[c] = v;
    }
}

// ---------------- launch ----------------
extern "C" void kernel_launch(void* const* d_in, const int* in_sizes, int n_in,
                              void* d_out, int out_size) {
    const float* x = nullptr;
    const float* w = nullptr;
    const float* b = nullptr;
    for (int i = 0; i < n_in; i++) {
        if (in_sizes[i] == NB * DIM) x = (const float*)d_in[i];
        else if (in_sizes[i] == DIM * DIM) w = (const float*)d_in[i];
        else if (in_sizes[i] == DIM) b = (const float*)d_in[i];
    }
    float* out = (float*)d_out;

    k_prep<<<NB + 4096 + 1, 256>>>(x, w, b);

    cudaFuncSetAttribute(k_gemm, cudaFuncAttributeMaxDynamicSharedMemorySize, SMEM_NEED);
    k_gemm<<<2048, 256, SMEM_NEED>>>();

    k_fin<<<NB, 256>>>(out);
}